// round 4
// baseline (speedup 1.0000x reference)
#include <cuda_runtime.h>
#include <cuda_bf16.h>
#include <cstdint>
#include <cstddef>

// ---------------------------------------------------------------------------
// Problem constants
// ---------------------------------------------------------------------------
#define NG    128
#define GSZ   128
#define DIM   512
#define NTOT  (NG * GSZ)               // 16384
#define NPAIR (GSZ * (GSZ - 1) / 2)    // 8128
#define NT    128                      // 128x128 tiles per dim

// GEMM tiling: CTA output tile 128x128, A resident full-K, B streamed
#define SEG    4                       // B tiles per CTA
#define NSEGMX 32                      // ceil(128/SEG)
#define THREADS 256
#define CHUNK_BYTES 16384              // 128 rows x 64 bf16 (128B, swizzled)
#define SOFF_B  (8 * CHUNK_BYTES)      // A = 8 chunks = 128KB
#define SMEM_TOTAL (SOFF_B + 4 * CHUNK_BYTES)  // +B ring 64KB = 192KB

// ---------------------------------------------------------------------------
// Device globals
// ---------------------------------------------------------------------------
__device__ __align__(16) __nv_bfloat16 g_Ebf[(size_t)NTOT * DIM];   // 16 MB
__device__ float g_scratch[(size_t)NG * GSZ * GSZ];                 // 8 MB
__device__ unsigned g_min_key;
__device__ unsigned g_max_key;

__device__ __forceinline__ unsigned f2key(float f) {
    unsigned b = __float_as_uint(f);
    return (b & 0x80000000u) ? ~b : (b | 0x80000000u);
}
__device__ __forceinline__ float key2f(unsigned k) {
    unsigned b = (k & 0x80000000u) ? (k ^ 0x80000000u) : ~k;
    return __uint_as_float(b);
}

// ---------------------------------------------------------------------------
// PTX helpers (baseline sm_80+ only)
// ---------------------------------------------------------------------------
__device__ __forceinline__ uint32_t smem_u32(const void* p) {
    uint32_t a;
    asm("{ .reg .u64 t; cvta.to.shared.u64 t, %1; cvt.u32.u64 %0, t; }" : "=r"(a) : "l"(p));
    return a;
}

#define CP_ASYNC16(s, g) \
    asm volatile("cp.async.cg.shared.global [%0], [%1], 16;" :: "r"(s), "l"(g) : "memory")
#define CP_COMMIT() asm volatile("cp.async.commit_group;" ::: "memory")

__device__ __forceinline__ void cp_wait_n(int n) {
    if (n >= 3)      asm volatile("cp.async.wait_group 3;" ::: "memory");
    else if (n == 2) asm volatile("cp.async.wait_group 2;" ::: "memory");
    else if (n == 1) asm volatile("cp.async.wait_group 1;" ::: "memory");
    else             asm volatile("cp.async.wait_group 0;" ::: "memory");
}

#define LDMATRIX_X4(r0, r1, r2, r3, addr) \
    asm volatile("ldmatrix.sync.aligned.m8n8.x4.shared.b16 {%0,%1,%2,%3}, [%4];" \
        : "=r"(r0), "=r"(r1), "=r"(r2), "=r"(r3) : "r"(addr))

#define MMA_16816(c0, c1, c2, c3, a0, a1, a2, a3, b0, b1) \
    asm volatile("mma.sync.aligned.m16n8k16.row.col.f32.bf16.bf16.f32 " \
        "{%0,%1,%2,%3}, {%4,%5,%6,%7}, {%8,%9}, {%0,%1,%2,%3};" \
        : "+f"(c0), "+f"(c1), "+f"(c2), "+f"(c3) \
        : "r"(a0), "r"(a1), "r"(a2), "r"(a3), "r"(b0), "r"(b1))

__device__ __forceinline__ uint32_t swz(uint32_t off) {
    return off ^ ((off >> 3) & 0x70);
}

// ---------------------------------------------------------------------------
// fp32 -> bf16 convert (8 elems/thread) + fused min/max key init
// ---------------------------------------------------------------------------
__device__ __forceinline__ uint32_t pack_bf2(float a, float b) {
    uint32_t lo = (uint32_t)__bfloat16_as_ushort(__float2bfloat16_rn(a));
    uint32_t hi = (uint32_t)__bfloat16_as_ushort(__float2bfloat16_rn(b));
    return lo | (hi << 16);
}

__global__ __launch_bounds__(256) void lp_convert_kernel(const float* __restrict__ E) {
    if (blockIdx.x == 0 && threadIdx.x == 0) {
        g_min_key = 0xFFFFFFFFu;
        g_max_key = 0u;
    }
    size_t t = (size_t)blockIdx.x * blockDim.x + threadIdx.x;
    const float4* src = (const float4*)(E + t * 8);
    float4 f0 = src[0], f1 = src[1];
    uint4 p = make_uint4(pack_bf2(f0.x, f0.y), pack_bf2(f0.z, f0.w),
                         pack_bf2(f1.x, f1.y), pack_bf2(f1.z, f1.w));
    *(uint4*)(g_Ebf + t * 8) = p;
}

// ---------------------------------------------------------------------------
// Persistent-segment GEMM.
// grid (NSEGMX, 128): blockIdx.y = ti; segment covers tj = ti + seg*SEG ...
// A (128 rows x 512 k) resident in SMEM (8 swizzled 16KB chunks);
// B streamed through a 4-stage 16KB ring (prefetch distance 3).
// 8 warps, warp tile 32x64. Fragments double-buffered across kk.
// ---------------------------------------------------------------------------
__global__ __launch_bounds__(THREADS, 1) void lp_mm_kernel() {
    const int ti = blockIdx.y;
    const int t0 = ti + blockIdx.x * SEG;
    if (t0 >= NT) return;
    const int ntiles = min(SEG, NT - t0);
    const int total = ntiles * 8;         // B k-chunks in this segment

    extern __shared__ __align__(128) unsigned char smem[];
    const uint32_t sb = smem_u32(smem);

    const int tid  = threadIdx.x;
    const int wid  = tid >> 5;
    const int lane = tid & 31;
    const int wm   = (wid >> 1) * 32;     // 0,32,64,96
    const int wn   = (wid & 1) * 64;      // 0 or 64

    const __nv_bfloat16* __restrict__ Abase = g_Ebf + (size_t)ti * GSZ * DIM;

    // ---- A: load all 8 chunks as ONE commit group (128 KB) ----
    {
        const int row = tid >> 1;              // 0..127
        const int c8h = (tid & 1) * 4;         // first/second half of the row's 8 chunks? no:
        // simpler: 32 copies/thread: chunk c (0..7), i (0..3)
        #pragma unroll
        for (int c = 0; c < 8; c++) {
            #pragma unroll
            for (int i = 0; i < 4; i++) {
                int id = tid + i * THREADS;    // 0..1023
                int r  = id >> 3, k8 = id & 7;
                CP_ASYNC16(sb + c * CHUNK_BYTES + swz((uint32_t)(r * 128 + k8 * 16)),
                           Abase + (size_t)r * DIM + c * 64 + k8 * 8);
            }
        }
        (void)row; (void)c8h;
    }
    CP_COMMIT();

    // ---- B chunk loader: global chunk q -> ring stage q&3 ----
    auto loadB = [&](int q) {
        const __nv_bfloat16* src = g_Ebf
            + (size_t)(t0 + (q >> 3)) * GSZ * DIM + (q & 7) * 64;
        const uint32_t sbase = sb + SOFF_B + (q & 3) * CHUNK_BYTES;
        #pragma unroll
        for (int i = 0; i < 4; i++) {
            int id = tid + i * THREADS;
            int r  = id >> 3, k8 = id & 7;
            CP_ASYNC16(sbase + swz((uint32_t)(r * 128 + k8 * 16)),
                       src + (size_t)r * DIM + k8 * 8);
        }
        CP_COMMIT();
    };

    // prologue: B chunks 0..2
    loadB(0); loadB(1); loadB(2);

    // per-thread fragment coordinates (identical math to round-3, validated)
    const int arow_lo = (lane & 15);
    const int akb     = ((lane >> 4) << 4);
    const int brow_in = ((lane >> 4) << 3) + (lane & 7);
    const int bkb     = ((lane >> 3) & 1) << 4;

    float gmin = 3.4e38f, gmax = -3.4e38f;
    float acc[2][8][4];

    for (int t = 0; t < ntiles; t++) {
        #pragma unroll
        for (int mt = 0; mt < 2; mt++)
            #pragma unroll
            for (int n8 = 0; n8 < 8; n8++)
                #pragma unroll
                for (int r = 0; r < 4; r++)
                    acc[mt][n8][r] = 0.0f;

        for (int kt = 0; kt < 8; kt++) {
            const int q = t * 8 + kt;
            if (q + 3 < total) loadB(q + 3);
            cp_wait_n(min(3, total - 1 - q));
            __syncthreads();

            const uint32_t sA = sb + kt * CHUNK_BYTES;
            const uint32_t sB = sb + SOFF_B + (q & 3) * CHUNK_BYTES;

            uint32_t a[2][2][4], b[2][4][4];
            // fragment loader for one kk
            auto ldfrag = [&](int kk, uint32_t A[2][4], uint32_t B[4][4]) {
                #pragma unroll
                for (int mt = 0; mt < 2; mt++) {
                    int row = wm + mt * 16 + arow_lo;
                    uint32_t kb = (uint32_t)(kk * 32 + akb);
                    uint32_t addr = sA + row * 128 + (kb ^ ((row & 7) << 4));
                    LDMATRIX_X4(A[mt][0], A[mt][1], A[mt][2], A[mt][3], addr);
                }
                #pragma unroll
                for (int nb = 0; nb < 4; nb++) {
                    int row = wn + nb * 16 + brow_in;
                    uint32_t kb = (uint32_t)(kk * 32 + bkb);
                    uint32_t addr = sB + row * 128 + (kb ^ ((row & 7) << 4));
                    LDMATRIX_X4(B[nb][0], B[nb][1], B[nb][2], B[nb][3], addr);
                }
            };

            ldfrag(0, a[0], b[0]);
            #pragma unroll
            for (int kk = 0; kk < 4; kk++) {
                const int cur = kk & 1;
                if (kk < 3) ldfrag(kk + 1, a[cur ^ 1], b[cur ^ 1]);
                #pragma unroll
                for (int mt = 0; mt < 2; mt++)
                    #pragma unroll
                    for (int nb = 0; nb < 4; nb++) {
                        MMA_16816(acc[mt][2*nb][0], acc[mt][2*nb][1],
                                  acc[mt][2*nb][2], acc[mt][2*nb][3],
                                  a[cur][mt][0], a[cur][mt][1], a[cur][mt][2], a[cur][mt][3],
                                  b[cur][nb][0], b[cur][nb][1]);
                        MMA_16816(acc[mt][2*nb+1][0], acc[mt][2*nb+1][1],
                                  acc[mt][2*nb+1][2], acc[mt][2*nb+1][3],
                                  a[cur][mt][0], a[cur][mt][1], a[cur][mt][2], a[cur][mt][3],
                                  b[cur][nb][2], b[cur][nb][3]);
                    }
            }
            __syncthreads();
        }

        // per-tile epilogue (registers only)
        #pragma unroll
        for (int mt = 0; mt < 2; mt++)
            #pragma unroll
            for (int n8 = 0; n8 < 8; n8++)
                #pragma unroll
                for (int r = 0; r < 4; r++) {
                    float v = acc[mt][n8][r];
                    gmin = fminf(gmin, v);
                    gmax = fmaxf(gmax, v);
                }

        if (t0 + t == ti) {   // diagonal tile: spill raw fp32 (tile == graph)
            float* s = g_scratch + (size_t)ti * GSZ * GSZ;
            #pragma unroll
            for (int mt = 0; mt < 2; mt++)
                #pragma unroll
                for (int n8 = 0; n8 < 8; n8++)
                    #pragma unroll
                    for (int r = 0; r < 4; r++) {
                        int mg = wm + mt * 16 + (lane >> 2) + ((r >> 1) << 3);
                        int ng = wn + n8 * 8 + ((lane & 3) << 1) + (r & 1);
                        s[(size_t)mg * GSZ + ng] = acc[mt][n8][r];
                    }
        }
    }

    // block-level min/max reduce -> 2 atomics per CTA
    #pragma unroll
    for (int off = 16; off > 0; off >>= 1) {
        gmin = fminf(gmin, __shfl_xor_sync(0xffffffffu, gmin, off));
        gmax = fmaxf(gmax, __shfl_xor_sync(0xffffffffu, gmax, off));
    }
    __shared__ float red_min[8], red_max[8];
    if (lane == 0) { red_min[wid] = gmin; red_max[wid] = gmax; }
    __syncthreads();
    if (tid == 0) {
        float m = red_min[0], M = red_max[0];
        #pragma unroll
        for (int w = 1; w < 8; w++) {
            m = fminf(m, red_min[w]);
            M = fmaxf(M, red_max[w]);
        }
        atomicMin(&g_min_key, f2key(m));
        atomicMax(&g_max_key, f2key(M));
    }
}

// ---------------------------------------------------------------------------
// normalize: one block per (graph, row); output row is contiguous
// ---------------------------------------------------------------------------
__global__ __launch_bounds__(128) void lp_norm_kernel(float* __restrict__ out) {
    const int g = blockIdx.x >> 7;
    const int r = blockIdx.x & 127;
    const int c = threadIdx.x;
    const float m = key2f(g_min_key);
    const float M = key2f(g_max_key);
    const float inv = 1.0f / (M - m + 1e-7f);
    if (c > r) {
        const float v = g_scratch[(((size_t)g * GSZ) + r) * GSZ + c];
        const int p = r * (GSZ - 1) - (r * (r - 1)) / 2 + (c - r - 1);
        out[(size_t)g * NPAIR + p] = (v - m) * inv;
    }
}

// ---------------------------------------------------------------------------
// kernel_launch
// ---------------------------------------------------------------------------
extern "C" void kernel_launch(void* const* d_in, const int* in_sizes, int n_in,
                              void* d_out, int out_size)
{
    const float* E = (const float*)d_in[0];
    float* out = (float*)d_out;
    (void)in_sizes; (void)n_in; (void)out_size;

    static bool attr_set = false;
    if (!attr_set) {
        cudaFuncSetAttribute(lp_mm_kernel,
                             cudaFuncAttributeMaxDynamicSharedMemorySize, SMEM_TOTAL);
        attr_set = true;
    }

    lp_convert_kernel<<<4096, 256>>>(E);
    lp_mm_kernel<<<dim3(NSEGMX, NT), THREADS, SMEM_TOTAL>>>();
    lp_norm_kernel<<<NG * GSZ, 128>>>(out);
}